// round 15
// baseline (speedup 1.0000x reference)
#include <cuda_runtime.h>
#include <math.h>
#include <stdint.h>

#define BSZ 16
#define NN_ 1024
#define DD_ 128
#define HH_ 8

// ---------------------------------------------------------------------------
// Static scratch
// ---------------------------------------------------------------------------
__device__ float g_q   [BSZ * NN_ * HH_ * DD_];      // [b,n,hd] tf32, pre-scaled
__device__ float g_k   [BSZ * NN_ * HH_ * DD_];      // [b,n,hd] tf32
__device__ float g_vt  [BSZ * NN_ * HH_ * DD_];      // [b,hd,n] tf32 (V^T)
__device__ float g_ctx [BSZ * NN_ * HH_ * DD_];      // [b,n,hd]
__device__ float g_hwt [BSZ * NN_ * DD_];            // [b,d,n]  (hw^T)
__device__ float g_feat[BSZ * NN_ * DD_];
__device__ float g_norm[BSZ * NN_ * DD_];
__device__ float g_wqT [NN_ * DD_];
__device__ float g_wkT [NN_ * DD_];
__device__ float g_wvT [NN_ * DD_];
__device__ float g_w2T [DD_ * NN_];                  // (Wo@Wg)^T [128,1024]
__device__ float g_wgT [DD_ * DD_];
__device__ float g_b2  [DD_];                        // bo @ Wg

// ---------------------------------------------------------------------------
__device__ __forceinline__ uint32_t tf32r(float x) {
    uint32_t u;
    asm("cvt.rna.tf32.f32 %0, %1;" : "=r"(u) : "f"(x));
    return u;
}
__device__ __forceinline__ void mma_tf32(float* d, const uint32_t* a, const uint32_t* b) {
    asm volatile(
        "mma.sync.aligned.m16n8k8.row.col.f32.tf32.tf32.f32 "
        "{%0,%1,%2,%3}, {%4,%5,%6,%7}, {%8,%9}, {%0,%1,%2,%3};"
        : "+f"(d[0]), "+f"(d[1]), "+f"(d[2]), "+f"(d[3])
        : "r"(a[0]), "r"(a[1]), "r"(a[2]), "r"(a[3]), "r"(b[0]), "r"(b[1]));
}
__device__ __forceinline__ uint4 cvt4(float4 v) {
    uint4 u;
    u.x = tf32r(v.x); u.y = tf32r(v.y); u.z = tf32r(v.z); u.w = tf32r(v.w);
    return u;
}

// ---------------------------------------------------------------------------
// Merged QKV GEMM with fused timestep embedding.
// A = F_c[b] (+ emb[n] broadcast over d), B = wqT/wkT/wvT [1024,128],
// C: Q/K row-major [n,hd]; V transposed -> vt [hd,n]. tf32-rounded outputs.
// grid (8, 8, 48): z = mat*16 + b.
// ---------------------------------------------------------------------------
__global__ void __launch_bounds__(256)
gemm_qkv(const float* __restrict__ F_c, const int* __restrict__ tt,
         const float* __restrict__ wqT, const float* __restrict__ wkT,
         const float* __restrict__ wvT,
         const float* __restrict__ bq, const float* __restrict__ bk,
         const float* __restrict__ bv,
         float* __restrict__ Qo, float* __restrict__ Ko, float* __restrict__ Vto) {
    __shared__ uint32_t sA[2][2048];
    __shared__ uint32_t sB[2][2048];

    const int tid  = threadIdx.x;
    const int wid  = tid >> 5;
    const int lane = tid & 31;
    const int warp_m = wid & 3;
    const int warp_n = wid >> 2;
    const int g   = lane >> 2;
    const int tig = lane & 3;

    const int z   = blockIdx.z;
    const int mat = z >> 4;            // 0=Q 1=K 2=V
    const int b   = z & 15;

    const size_t sBD = (size_t)NN_ * DD_;
    const size_t sBN = (size_t)NN_ * HH_ * DD_;
    const float* A    = F_c + (size_t)b * sBD;
    const float* B    = (mat == 0) ? wqT : (mat == 1) ? wkT : wvT;
    const float* bias = (mat == 0) ? bq  : (mat == 1) ? bk  : bv;
    const float alpha = (mat == 0) ? 0.08838834764831845f : 1.0f;

    const int m0 = blockIdx.y * 128, n0 = blockIdx.x * 128;

    const int sw = wid;
    const int qk = lane >> 3;
    const int gg = lane & 7;
    const int rk = qk & 1, kk0 = qk >> 1;

    const uint32_t aSt0 = ((((((sw >> 1) * 2 + kk0) * 2) + (sw & 1)) * 4 + rk * 2) * 32) + gg * 4;
    const uint32_t aSt1 = aSt0 + 32;
    const uint32_t bSt0 = (((((sw >> 2) * 2 + kk0) * 8 + ((sw * 2) & 7)) * 2 + rk) * 32) + gg * 4;
    const uint32_t bSt1 = bSt0 + 64;

    // embedding for this thread's two A rows (constant across k-tiles)
    const int n0r = m0 + sw * 16 + gg;
    const int n1r = n0r + 8;
    const float tv = (float)tt[b];
    const float kC = logf(1000.0f) / 511.0f;
    float e0, e1;
    {
        int i0 = (n0r < 512) ? n0r : (n0r - 512);
        float ee0 = tv * __expf(-(float)i0 * kC);
        e0 = (n0r < 512) ? sinf(ee0) : cosf(ee0);
        int i1 = (n1r < 512) ? n1r : (n1r - 512);
        float ee1 = tv * __expf(-(float)i1 * kC);
        e1 = (n1r < 512) ? sinf(ee1) : cosf(ee1);
    }

    const float* Ap = A + (size_t)n0r * DD_ + qk * 4;
    const float* Bp = B + (size_t)(n0 + sw * 16 + gg) * DD_ + qk * 4;
    const size_t a8 = (size_t)8 * DD_, b8 = (size_t)8 * DD_;

    float acc[2][8][4];
    #pragma unroll
    for (int mt = 0; mt < 2; mt++)
        #pragma unroll
        for (int nt = 0; nt < 8; nt++)
            #pragma unroll
            for (int r = 0; r < 4; r++) acc[mt][nt][r] = 0.0f;

    auto addv = [](float4 v, float e) {
        v.x += e; v.y += e; v.z += e; v.w += e;
        return v;
    };

    float4 ra0, ra1, rb0, rb1;
    ra0 = *(const float4*)(Ap);
    ra1 = *(const float4*)(Ap + a8);
    rb0 = *(const float4*)(Bp);
    rb1 = *(const float4*)(Bp + b8);
    *(uint4*)&sA[0][aSt0] = cvt4(addv(ra0, e0));
    *(uint4*)&sA[0][aSt1] = cvt4(addv(ra1, e1));
    *(uint4*)&sB[0][bSt0] = cvt4(rb0);
    *(uint4*)&sB[0][bSt1] = cvt4(rb1);
    __syncthreads();

    #pragma unroll 4
    for (int kt = 0; kt < 8; kt++) {
        const int cur = kt & 1;
        if (kt + 1 < 8) {
            const int k0 = (kt + 1) << 4;
            ra0 = *(const float4*)(Ap + k0);
            ra1 = *(const float4*)(Ap + k0 + a8);
            rb0 = *(const float4*)(Bp + k0);
            rb1 = *(const float4*)(Bp + k0 + b8);
        }
        const uint32_t* aB = sA[cur];
        const uint32_t* bB = sB[cur];
        #pragma unroll
        for (int kk = 0; kk < 2; kk++) {
            uint32_t af[2][4];
            #pragma unroll
            for (int mt = 0; mt < 2; mt++) {
                const uint32_t base = (((warp_m * 2 + kk) * 2 + mt) * 4) * 32 + lane;
                af[mt][0] = aB[base];
                af[mt][1] = aB[base + 32];
                af[mt][2] = aB[base + 64];
                af[mt][3] = aB[base + 96];
            }
            uint32_t bf[8][2];
            #pragma unroll
            for (int nt = 0; nt < 8; nt++) {
                const uint32_t base = ((((warp_n * 2 + kk) * 8 + nt) * 2) * 32) + lane;
                bf[nt][0] = bB[base];
                bf[nt][1] = bB[base + 32];
            }
            #pragma unroll
            for (int mt = 0; mt < 2; mt++)
                #pragma unroll
                for (int nt = 0; nt < 8; nt++)
                    mma_tf32(acc[mt][nt], af[mt], bf[nt]);
        }
        if (kt + 1 < 8) {
            const int nxt = cur ^ 1;
            __syncthreads();
            *(uint4*)&sA[nxt][aSt0] = cvt4(addv(ra0, e0));
            *(uint4*)&sA[nxt][aSt1] = cvt4(addv(ra1, e1));
            *(uint4*)&sB[nxt][bSt0] = cvt4(rb0);
            *(uint4*)&sB[nxt][bSt1] = cvt4(rb1);
            __syncthreads();
        }
    }

    float* Crow = ((mat == 0) ? Qo : Ko) + (size_t)b * sBN;   // [n, hd]
    float* Cct  = Vto + (size_t)b * sBN;                       // [hd, n]
    #pragma unroll
    for (int mt = 0; mt < 2; mt++) {
        const int row = m0 + warp_m * 32 + mt * 16 + g;
        #pragma unroll
        for (int nt = 0; nt < 8; nt++) {
            const int col = n0 + warp_n * 64 + nt * 8 + tig * 2;
            float b0 = bias[col], b1 = bias[col + 1];
            float v0 = (acc[mt][nt][0] + b0) * alpha;
            float v1 = (acc[mt][nt][1] + b1) * alpha;
            float v2 = (acc[mt][nt][2] + b0) * alpha;
            float v3 = (acc[mt][nt][3] + b1) * alpha;
            v0 = __uint_as_float(tf32r(v0));
            v1 = __uint_as_float(tf32r(v1));
            v2 = __uint_as_float(tf32r(v2));
            v3 = __uint_as_float(tf32r(v3));
            if (mat == 2) {
                Cct[(size_t)col * NN_ + row]           = v0;
                Cct[(size_t)(col + 1) * NN_ + row]     = v1;
                Cct[(size_t)col * NN_ + row + 8]       = v2;
                Cct[(size_t)(col + 1) * NN_ + row + 8] = v3;
            } else {
                *(float2*)(Crow + (size_t)row * (HH_ * DD_) + col)       = make_float2(v0, v1);
                *(float2*)(Crow + (size_t)(row + 8) * (HH_ * DD_) + col) = make_float2(v2, v3);
            }
        }
    }
}

// ---------------------------------------------------------------------------
// Fused flash attention (round-11 structure: K-tile 64, 1 CTA/SM,
// register-prefetch, max-free softmax, column-split QK).
// ---------------------------------------------------------------------------
__global__ void __launch_bounds__(256) k_flash(
    const float* __restrict__ Qg, const float* __restrict__ Kg,
    const float* __restrict__ Vt, float* __restrict__ Cx) {
    extern __shared__ uint32_t dsm[];
    uint32_t* sQ = dsm;                         // 16384 words
    uint32_t* sK = dsm + 16384;                 //  8192
    uint32_t* sV = dsm + 24576;                 //  8192
    uint32_t* sP = dsm + 32768;                 //  8192
    float*    lS = (float*)(dsm + 40960);       //   256 floats

    const int tid = threadIdx.x;
    const int w = tid >> 5, l = tid & 31;
    const int g = l >> 2, tig = l & 3;
    const int gg = l & 7, s = l >> 3;
    const int rg = w & 3, ch = w >> 2;
    const int b = blockIdx.y >> 3, h = blockIdx.y & 7;
    const int qt = blockIdx.x;

    const size_t sBN = (size_t)NN_ * HH_ * DD_;
    const float* qp = Qg + (size_t)b * sBN + (size_t)qt * 128 * 1024 + h * 128;
    const float* kp = Kg + (size_t)b * sBN + h * 128;
    const float* vp = Vt + (size_t)b * sBN + (size_t)(h * 128) * 1024;
    float*       cp = Cx + (size_t)b * sBN + (size_t)qt * 128 * 1024 + h * 128;

    // ---- stage Q ----
    {
        const int r  = w * 16 + gg + (s & 1) * 8;
        const int rm = s & 1;
        const float* src = qp + (size_t)r * 1024;
        #pragma unroll
        for (int i = 0; i < 16; i++) {
            const int qd = (s >> 1) + i * 2;
            uint4 v = *(const uint4*)(src + qd * 4);
            const uint32_t base =
                (uint32_t)((((w * 16 + (qd >> 1)) * 4 + (qd & 1) * 2 + rm) * 32) + gg * 4);
            *(uint4*)&sQ[base] = v;
        }
    }

    const float* kRow = kp + (size_t)(w * 8 + gg) * 1024;
    const int vdd = w * 16 + gg + (s & 1) * 8;
    const float* vRow = vp + (size_t)vdd * 1024;

    uint4 rK[8], rV[8];
    #pragma unroll
    for (int i = 0; i < 8; i++) {
        rK[i] = *(const uint4*)(kRow + (s + i * 4) * 4);
        rV[i] = *(const uint4*)(vRow + ((s >> 1) + i * 2) * 4);
    }

    float lp[2][2] = {};
    float o[2][8][4];
    #pragma unroll
    for (int mt = 0; mt < 2; mt++)
        #pragma unroll
        for (int nt = 0; nt < 8; nt++)
            #pragma unroll
            for (int r = 0; r < 4; r++) o[mt][nt][r] = 0.0f;

    for (int kt = 0; kt < 16; kt++) {
        __syncthreads();
        #pragma unroll
        for (int i = 0; i < 8; i++) {
            const int qd = s + i * 4;
            const uint32_t base =
                (uint32_t)(((((qd >> 1) * 8 + w) * 2 + (qd & 1)) * 32) + gg * 4);
            *(uint4*)&sK[base] = rK[i];
        }
        #pragma unroll
        for (int i = 0; i < 8; i++) {
            const int qd = (s >> 1) + i * 2;
            const uint32_t base =
                (uint32_t)(((((qd >> 1) * 16 + (vdd >> 3)) * 2 + (qd & 1)) * 32) + gg * 4);
            *(uint4*)&sV[base] = rV[i];
        }
        __syncthreads();

        if (kt + 1 < 16) {
            const float* kn = kRow + (size_t)(kt + 1) * 64 * 1024;
            const float* vn = vRow + (kt + 1) * 64;
            #pragma unroll
            for (int i = 0; i < 8; i++) {
                rK[i] = *(const uint4*)(kn + (s + i * 4) * 4);
                rV[i] = *(const uint4*)(vn + ((s >> 1) + i * 2) * 4);
            }
        }

        // ---- S = Qs @ K^T ----
        float sc[2][4][4];
        #pragma unroll
        for (int mt = 0; mt < 2; mt++)
            #pragma unroll
            for (int nt = 0; nt < 4; nt++)
                #pragma unroll
                for (int r = 0; r < 4; r++) sc[mt][nt][r] = 0.0f;
        #pragma unroll
        for (int kc = 0; kc < 16; kc++) {
            uint32_t af[2][4];
            #pragma unroll
            for (int mt = 0; mt < 2; mt++) {
                const uint32_t ab = (uint32_t)((((rg * 2 + mt) * 16 + kc) * 4) * 32 + l);
                af[mt][0] = sQ[ab];      af[mt][1] = sQ[ab + 32];
                af[mt][2] = sQ[ab + 64]; af[mt][3] = sQ[ab + 96];
            }
            #pragma unroll
            for (int nt = 0; nt < 4; nt++) {
                const uint32_t bb = (uint32_t)(((kc * 8 + ch * 4 + nt) * 2) * 32 + l);
                uint32_t bf[2] = {sK[bb], sK[bb + 32]};
                mma_tf32(sc[0][nt], af[0], bf);
                mma_tf32(sc[1][nt], af[1], bf);
            }
        }

        // ---- max-free softmax ----
        #pragma unroll
        for (int mt = 0; mt < 2; mt++) {
            #pragma unroll
            for (int nt = 0; nt < 4; nt++) {
                const float p0 = __expf(sc[mt][nt][0]);
                const float p1 = __expf(sc[mt][nt][1]);
                const float p2 = __expf(sc[mt][nt][2]);
                const float p3 = __expf(sc[mt][nt][3]);
                lp[mt][0] += p0 + p1;
                lp[mt][1] += p2 + p3;
                const uint32_t wb =
                    (uint32_t)((((rg * 2 + mt) * 8 + ch * 4 + nt) * 4 + (tig >> 1) * 2) * 32)
                    + g * 4 + (tig & 1) * 2;
                uint2 lo, hi;
                lo.x = tf32r(p0); lo.y = tf32r(p1);
                hi.x = tf32r(p2); hi.y = tf32r(p3);
                *(uint2*)&sP[wb]      = lo;
                *(uint2*)&sP[wb + 32] = hi;
            }
        }
        __syncthreads();

        // ---- O += P @ V ----
        #pragma unroll
        for (int kc = 0; kc < 8; kc++) {
            uint32_t af[2][4];
            #pragma unroll
            for (int mt = 0; mt < 2; mt++) {
                const uint32_t ab = (uint32_t)((((rg * 2 + mt) * 8 + kc) * 4) * 32 + l);
                af[mt][0] = sP[ab];      af[mt][1] = sP[ab + 32];
                af[mt][2] = sP[ab + 64]; af[mt][3] = sP[ab + 96];
            }
            #pragma unroll
            for (int nt = 0; nt < 8; nt++) {
                const uint32_t bb = (uint32_t)(((kc * 16 + ch * 8 + nt) * 2) * 32 + l);
                uint32_t bf[2] = {sV[bb], sV[bb + 32]};
                mma_tf32(o[0][nt], af[0], bf);
                mma_tf32(o[1][nt], af[1], bf);
            }
        }
    }

    // ---- combine l partials ----
    #pragma unroll
    for (int mt = 0; mt < 2; mt++)
        #pragma unroll
        for (int rm = 0; rm < 2; rm++) {
            lp[mt][rm] += __shfl_xor_sync(~0u, lp[mt][rm], 1);
            lp[mt][rm] += __shfl_xor_sync(~0u, lp[mt][rm], 2);
        }
    if (tig == 0) {
        lS[ch * 128 + rg * 32 + g]          = lp[0][0];
        lS[ch * 128 + rg * 32 + g + 8]      = lp[0][1];
        lS[ch * 128 + rg * 32 + 16 + g]     = lp[1][0];
        lS[ch * 128 + rg * 32 + 16 + g + 8] = lp[1][1];
    }
    __syncthreads();

    const float iA0 = 1.0f / (lS[rg * 32 + g]          + lS[128 + rg * 32 + g]);
    const float iA1 = 1.0f / (lS[rg * 32 + g + 8]      + lS[128 + rg * 32 + g + 8]);
    const float iB0 = 1.0f / (lS[rg * 32 + 16 + g]     + lS[128 + rg * 32 + 16 + g]);
    const float iB1 = 1.0f / (lS[rg * 32 + 16 + g + 8] + lS[128 + rg * 32 + 16 + g + 8]);
    float* r0p = cp + (size_t)(rg * 32 + g) * 1024;
    float* r1p = cp + (size_t)(rg * 32 + g + 8) * 1024;
    float* r2p = cp + (size_t)(rg * 32 + 16 + g) * 1024;
    float* r3p = cp + (size_t)(rg * 32 + 16 + g + 8) * 1024;
    #pragma unroll
    for (int nt = 0; nt < 8; nt++) {
        const int col = ch * 64 + nt * 8 + tig * 2;
        *(float2*)(r0p + col) = make_float2(o[0][nt][0] * iA0, o[0][nt][1] * iA0);
        *(float2*)(r1p + col) = make_float2(o[0][nt][2] * iA1, o[0][nt][3] * iA1);
        *(float2*)(r2p + col) = make_float2(o[1][nt][0] * iB0, o[1][nt][1] * iB0);
        *(float2*)(r3p + col) = make_float2(o[1][nt][2] * iB1, o[1][nt][3] * iB1);
    }
}

// ---------------------------------------------------------------------------
// tf32 GEMM (K templated): C = alpha*(A@B^T + bias) (+relu), opt C^T/tf32 out.
// SYM: blockIdx.x encodes upper-triangle block pair of an 8x8 grid; mirrors.
// ---------------------------------------------------------------------------
template<bool RELU, bool HASBIAS, bool CT, bool TF32OUT, int KT, bool SYM>
__global__ void __launch_bounds__(256)
gemm_tb(const float* __restrict__ A, int lda, size_t aOut, size_t aIn,
        const float* __restrict__ B, int ldb, size_t bOut, size_t bIn,
        float*       __restrict__ C, int ldc, size_t cOut, size_t cIn,
        const float* __restrict__ bias,
        int zInner, float alpha) {
    __shared__ uint32_t sA[2][2048];
    __shared__ uint32_t sB[2][2048];

    const int tid  = threadIdx.x;
    const int wid  = tid >> 5;
    const int lane = tid & 31;
    const int warp_m = wid & 3;
    const int warp_n = wid >> 2;
    const int g   = lane >> 2;
    const int tig = lane & 3;

    int z  = blockIdx.z;
    int zo = z / zInner, zi = z - zo * zInner;
    A += (size_t)zo * aOut + (size_t)zi * aIn;
    B += (size_t)zo * bOut + (size_t)zi * bIn;
    C += (size_t)zo * cOut + (size_t)zi * cIn;

    int xb = blockIdx.x, yb = blockIdx.y;
    if (SYM) {
        int idx = blockIdx.x, y = 0;
        while (idx >= 8 - y) { idx -= 8 - y; y++; }
        yb = y; xb = y + idx;
    }
    const int m0 = yb * 128, n0 = xb * 128;

    const int sw = wid;
    const int qk = lane >> 3;
    const int gg = lane & 7;
    const int rk = qk & 1, kk0 = qk >> 1;

    const uint32_t aSt0 = ((((((sw >> 1) * 2 + kk0) * 2) + (sw & 1)) * 4 + rk * 2) * 32) + gg * 4;
    const uint32_t aSt1 = aSt0 + 32;
    const uint32_t bSt0 = (((((sw >> 2) * 2 + kk0) * 8 + ((sw * 2) & 7)) * 2 + rk) * 32) + gg * 4;
    const uint32_t bSt1 = bSt0 + 64;

    const float* Ap = A + (size_t)(m0 + sw * 16 + gg) * lda + qk * 4;
    const float* Bp = B + (size_t)(n0 + sw * 16 + gg) * ldb + qk * 4;
    const size_t a8 = (size_t)8 * lda, b8 = (size_t)8 * ldb;

    float acc[2][8][4];
    #pragma unroll
    for (int mt = 0; mt < 2; mt++)
        #pragma unroll
        for (int nt = 0; nt < 8; nt++)
            #pragma unroll
            for (int r = 0; r < 4; r++) acc[mt][nt][r] = 0.0f;

    float4 ra0, ra1, rb0, rb1;
    ra0 = *(const float4*)(Ap);
    ra1 = *(const float4*)(Ap + a8);
    rb0 = *(const float4*)(Bp);
    rb1 = *(const float4*)(Bp + b8);
    *(uint4*)&sA[0][aSt0] = cvt4(ra0);
    *(uint4*)&sA[0][aSt1] = cvt4(ra1);
    *(uint4*)&sB[0][bSt0] = cvt4(rb0);
    *(uint4*)&sB[0][bSt1] = cvt4(rb1);
    __syncthreads();

    constexpr int nkt = KT >> 4;
    #pragma unroll 4
    for (int kt = 0; kt < nkt; kt++) {
        const int cur = kt & 1;
        if (kt + 1 < nkt) {
            const int k0 = (kt + 1) << 4;
            ra0 = *(const float4*)(Ap + k0);
            ra1 = *(const float4*)(Ap + k0 + a8);
            rb0 = *(const float4*)(Bp + k0);
            rb1 = *(const float4*)(Bp + k0 + b8);
        }
        const uint32_t* aB = sA[cur];
        const uint32_t* bB = sB[cur];
        #pragma unroll
        for (int kk = 0; kk < 2; kk++) {
            uint32_t af[2][4];
            #pragma unroll
            for (int mt = 0; mt < 2; mt++) {
                const uint32_t base = (((warp_m * 2 + kk) * 2 + mt) * 4) * 32 + lane;
                af[mt][0] = aB[base];
                af[mt][1] = aB[base + 32];
                af[mt][2] = aB[base + 64];
                af[mt][3] = aB[base + 96];
            }
            uint32_t bf[8][2];
            #pragma unroll
            for (int nt = 0; nt < 8; nt++) {
                const uint32_t base = ((((warp_n * 2 + kk) * 8 + nt) * 2) * 32) + lane;
                bf[nt][0] = bB[base];
                bf[nt][1] = bB[base + 32];
            }
            #pragma unroll
            for (int mt = 0; mt < 2; mt++)
                #pragma unroll
                for (int nt = 0; nt < 8; nt++)
                    mma_tf32(acc[mt][nt], af[mt], bf[nt]);
        }
        if (kt + 1 < nkt) {
            const int nxt = cur ^ 1;
            __syncthreads();
            *(uint4*)&sA[nxt][aSt0] = cvt4(ra0);
            *(uint4*)&sA[nxt][aSt1] = cvt4(ra1);
            *(uint4*)&sB[nxt][bSt0] = cvt4(rb0);
            *(uint4*)&sB[nxt][bSt1] = cvt4(rb1);
            __syncthreads();
        }
    }

    #pragma unroll
    for (int mt = 0; mt < 2; mt++) {
        const int row = m0 + warp_m * 32 + mt * 16 + g;
        #pragma unroll
        for (int nt = 0; nt < 8; nt++) {
            const int col = n0 + warp_n * 64 + nt * 8 + tig * 2;
            float v0 = acc[mt][nt][0];
            float v1 = acc[mt][nt][1];
            float v2 = acc[mt][nt][2];
            float v3 = acc[mt][nt][3];
            if (HASBIAS) {
                float b0 = bias[col], b1 = bias[col + 1];
                v0 += b0; v1 += b1; v2 += b0; v3 += b1;
            }
            v0 *= alpha; v1 *= alpha; v2 *= alpha; v3 *= alpha;
            if (RELU) {
                v0 = fmaxf(v0, 0.0f); v1 = fmaxf(v1, 0.0f);
                v2 = fmaxf(v2, 0.0f); v3 = fmaxf(v3, 0.0f);
            }
            if (TF32OUT) {
                v0 = __uint_as_float(tf32r(v0));
                v1 = __uint_as_float(tf32r(v1));
                v2 = __uint_as_float(tf32r(v2));
                v3 = __uint_as_float(tf32r(v3));
            }
            if (CT) {
                C[(size_t)col * ldc + row]           = v0;
                C[(size_t)(col + 1) * ldc + row]     = v1;
                C[(size_t)col * ldc + row + 8]       = v2;
                C[(size_t)(col + 1) * ldc + row + 8] = v3;
            } else {
                *(float2*)(C + (size_t)row * ldc + col)       = make_float2(v0, v1);
                *(float2*)(C + (size_t)(row + 8) * ldc + col) = make_float2(v2, v3);
                if (SYM && xb != yb) {
                    C[(size_t)col * ldc + row]           = v0;
                    C[(size_t)(col + 1) * ldc + row]     = v1;
                    C[(size_t)col * ldc + row + 8]       = v2;
                    C[(size_t)(col + 1) * ldc + row + 8] = v3;
                }
            }
        }
    }
}

// ---------------------------------------------------------------------------
__global__ void k_transpose(const float* __restrict__ in, float* __restrict__ out,
                            int R, int C) {
    __shared__ float t[32][33];
    int bx = blockIdx.x * 32, by = blockIdx.y * 32;
    #pragma unroll
    for (int i = 0; i < 32; i += 8)
        t[threadIdx.y + i][threadIdx.x] = in[(size_t)(by + threadIdx.y + i) * C + bx + threadIdx.x];
    __syncthreads();
    #pragma unroll
    for (int i = 0; i < 32; i += 8)
        out[(size_t)(bx + threadIdx.y + i) * R + by + threadIdx.x] = t[threadIdx.x][threadIdx.y + i];
}

__global__ void k_transpose3(const float* __restrict__ i0, float* __restrict__ o0,
                             const float* __restrict__ i1, float* __restrict__ o1,
                             const float* __restrict__ i2, float* __restrict__ o2) {
    __shared__ float t[32][33];
    const float* in = (blockIdx.z == 0) ? i0 : (blockIdx.z == 1) ? i1 : i2;
    float* out      = (blockIdx.z == 0) ? o0 : (blockIdx.z == 1) ? o1 : o2;
    const int C = HH_ * DD_, R = DD_;
    int bx = blockIdx.x * 32, by = blockIdx.y * 32;
    #pragma unroll
    for (int i = 0; i < 32; i += 8)
        t[threadIdx.y + i][threadIdx.x] = in[(size_t)(by + threadIdx.y + i) * C + bx + threadIdx.x];
    __syncthreads();
    #pragma unroll
    for (int i = 0; i < 32; i += 8)
        out[(size_t)(bx + threadIdx.y + i) * R + by + threadIdx.x] = t[threadIdx.x][threadIdx.y + i];
}

// ---------------------------------------------------------------------------
__global__ void k_bias2(const float* __restrict__ bo, const float* __restrict__ Wg,
                        float* __restrict__ b2) {
    int j = threadIdx.x;
    float s = 0.0f;
    for (int k = 0; k < DD_; k++) s += bo[k] * Wg[k * DD_ + j];
    b2[j] = s;
}

// ---------------------------------------------------------------------------
__global__ void k_rownorm(const float* __restrict__ feat,
                          float*       __restrict__ out) {
    int tid = threadIdx.x;
    size_t base = (size_t)blockIdx.x * DD_;
    float x = feat[base + tid];
    __shared__ float red[4];
    float s = x;
    #pragma unroll
    for (int o = 16; o > 0; o >>= 1) s += __shfl_xor_sync(0xffffffffu, s, o);
    if ((tid & 31) == 0) red[tid >> 5] = s;
    __syncthreads();
    float mu = (red[0] + red[1] + red[2] + red[3]) * (1.0f / 128.0f);
    float d = x - mu;
    float ss = d * d;
    #pragma unroll
    for (int o = 16; o > 0; o >>= 1) ss += __shfl_xor_sync(0xffffffffu, ss, o);
    __syncthreads();
    if ((tid & 31) == 0) red[tid >> 5] = ss;
    __syncthreads();
    float var = (red[0] + red[1] + red[2] + red[3]) * (1.0f / 127.0f);
    float inv = 1.0f / (sqrtf(var) + 1e-8f);
    out[base + tid] = d * inv;
}

// ---------------------------------------------------------------------------
extern "C" void kernel_launch(void* const* d_in, const int* in_sizes, int n_in,
                              void* d_out, int out_size) {
    const float* A_t = (const float*)d_in[0];
    const float* F_c = (const float*)d_in[1];
    const int*   t   = (const int*)  d_in[2];
    const float* Wq  = (const float*)d_in[3];
    const float* bq  = (const float*)d_in[4];
    const float* Wk  = (const float*)d_in[5];
    const float* bk  = (const float*)d_in[6];
    const float* Wv  = (const float*)d_in[7];
    const float* bv  = (const float*)d_in[8];
    const float* Wo  = (const float*)d_in[9];
    const float* bo  = (const float*)d_in[10];
    const float* Wg  = (const float*)d_in[11];
    float* out = (float*)d_out;

    float *q, *k, *vt, *ctx, *hwt, *feat, *nrm;
    float *wqT, *wkT, *wvT, *w2T, *wgT, *b2;
    cudaGetSymbolAddress((void**)&q,    g_q);
    cudaGetSymbolAddress((void**)&k,    g_k);
    cudaGetSymbolAddress((void**)&vt,   g_vt);
    cudaGetSymbolAddress((void**)&ctx,  g_ctx);
    cudaGetSymbolAddress((void**)&hwt,  g_hwt);
    cudaGetSymbolAddress((void**)&feat, g_feat);
    cudaGetSymbolAddress((void**)&nrm,  g_norm);
    cudaGetSymbolAddress((void**)&wqT,  g_wqT);
    cudaGetSymbolAddress((void**)&wkT,  g_wkT);
    cudaGetSymbolAddress((void**)&wvT,  g_wvT);
    cudaGetSymbolAddress((void**)&w2T,  g_w2T);
    cudaGetSymbolAddress((void**)&wgT,  g_wgT);
    cudaGetSymbolAddress((void**)&b2,   g_b2);

    const size_t sBN = (size_t)NN_ * HH_ * DD_;
    const size_t sBD = (size_t)NN_ * DD_;
    const size_t sNN = (size_t)NN_ * NN_;
    const int    HD  = HH_ * DD_;
    const int    FLASH_SMEM = 40960 * 4 + 1024;

    cudaFuncSetAttribute(k_flash, cudaFuncAttributeMaxDynamicSharedMemorySize, FLASH_SMEM);

    // (1) QKV weight transposes
    k_transpose3<<<dim3(32, 4, 3), dim3(32, 8)>>>(Wq, wqT, Wk, wkT, Wv, wvT);

    // (2) merged QKV GEMM with fused timestep embedding
    gemm_qkv<<<dim3(8, 8, 3 * BSZ), 256>>>(F_c, t, wqT, wkT, wvT,
                                           bq, bk, bv, q, k, vt);

    // (3) fused attention
    k_flash<<<dim3(8, BSZ * HH_), 256, FLASH_SMEM>>>(q, k, vt, ctx);

    // (4-6) merged Wo+Wg prep
    k_transpose<<<dim3(4, 4), dim3(32, 8)>>>(Wg, wgT, DD_, DD_);
    k_bias2<<<1, DD_>>>(bo, Wg, b2);
    gemm_tb<false, false, false, false, 128, false><<<dim3(8, 1, 1), 256>>>(
        wgT, DD_, 0, 0, Wo, DD_, 0, 0, w2T, NN_, 0, 0,
        nullptr, 1, 1.0f);

    // (7) hwt = (ctx @ W2 + b2)^T
    {
        dim3 g(1, 8, BSZ);
        gemm_tb<false, true, true, false, 1024, false><<<g, 256>>>(ctx, HD, sBN, 0,
                                                                   w2T, NN_, 0, 0,
                                                                   hwt, NN_, sBD, 0,
                                                                   b2, 1, 1.0f);
    }
    // (8) feat = relu(A_t @ hw)
    {
        dim3 g(1, 8, BSZ);
        gemm_tb<true, false, false, false, 1024, false><<<g, 256>>>(A_t, NN_, sNN, 0,
                                                                    hwt, NN_, sBD, 0,
                                                                    feat, DD_, sBD, 0,
                                                                    nullptr, 1, 1.0f);
    }
    // (9) row normalize
    k_rownorm<<<BSZ * NN_, DD_>>>(feat, nrm);

    // (10) out = (norm @ norm^T) / 128  — symmetric blocks, mirrored
    {
        dim3 g(36, 1, BSZ);
        gemm_tb<false, false, false, false, 128, true><<<g, 256>>>(nrm, DD_, sBD, 0,
                                                                   nrm, DD_, sBD, 0,
                                                                   out, NN_, sNN, 0,
                                                                   nullptr, 1, 1.0f / 128.0f);
    }
}

// round 16
// speedup vs baseline: 1.2732x; 1.2732x over previous
#include <cuda_runtime.h>
#include <math.h>
#include <stdint.h>

#define BSZ 16
#define NN_ 1024
#define DD_ 128
#define HH_ 8

// ---------------------------------------------------------------------------
// Static scratch
// ---------------------------------------------------------------------------
__device__ float g_c   [BSZ * NN_ * DD_];
__device__ float g_q   [BSZ * NN_ * HH_ * DD_];      // [b,n,hd] tf32, pre-scaled
__device__ float g_k   [BSZ * NN_ * HH_ * DD_];      // [b,n,hd] tf32
__device__ float g_vt  [BSZ * NN_ * HH_ * DD_];      // [b,hd,n] tf32 (V^T)
__device__ float g_ctx [BSZ * NN_ * HH_ * DD_];      // [b,n,hd]
__device__ float g_hwt [BSZ * NN_ * DD_];            // [b,d,n]  (hw^T)
__device__ float g_feat[BSZ * NN_ * DD_];
__device__ float g_norm[BSZ * NN_ * DD_];
__device__ float g_wqT [NN_ * DD_];
__device__ float g_wkT [NN_ * DD_];
__device__ float g_wvT [NN_ * DD_];
__device__ float g_w2T [DD_ * NN_];                  // (Wo@Wg)^T [128,1024]
__device__ float g_wgT [DD_ * DD_];
__device__ float g_b2  [DD_];                        // bo @ Wg

// ---------------------------------------------------------------------------
__device__ __forceinline__ uint32_t tf32r(float x) {
    uint32_t u;
    asm("cvt.rna.tf32.f32 %0, %1;" : "=r"(u) : "f"(x));
    return u;
}
__device__ __forceinline__ void mma_tf32(float* d, const uint32_t* a, const uint32_t* b) {
    asm volatile(
        "mma.sync.aligned.m16n8k8.row.col.f32.tf32.tf32.f32 "
        "{%0,%1,%2,%3}, {%4,%5,%6,%7}, {%8,%9}, {%0,%1,%2,%3};"
        : "+f"(d[0]), "+f"(d[1]), "+f"(d[2]), "+f"(d[3])
        : "r"(a[0]), "r"(a[1]), "r"(a[2]), "r"(a[3]), "r"(b[0]), "r"(b[1]));
}
__device__ __forceinline__ uint4 cvt4(float4 v) {
    uint4 u;
    u.x = tf32r(v.x); u.y = tf32r(v.y); u.z = tf32r(v.z); u.w = tf32r(v.w);
    return u;
}

// ---------------------------------------------------------------------------
// Fused flash attention (round-11 structure: K-tile 64, 1 CTA/SM,
// register-prefetch, max-free softmax, column-split QK).
// ---------------------------------------------------------------------------
__global__ void __launch_bounds__(256) k_flash(
    const float* __restrict__ Qg, const float* __restrict__ Kg,
    const float* __restrict__ Vt, float* __restrict__ Cx) {
    extern __shared__ uint32_t dsm[];
    uint32_t* sQ = dsm;                         // 16384 words
    uint32_t* sK = dsm + 16384;                 //  8192
    uint32_t* sV = dsm + 24576;                 //  8192
    uint32_t* sP = dsm + 32768;                 //  8192
    float*    lS = (float*)(dsm + 40960);       //   256 floats

    const int tid = threadIdx.x;
    const int w = tid >> 5, l = tid & 31;
    const int g = l >> 2, tig = l & 3;
    const int gg = l & 7, s = l >> 3;
    const int rg = w & 3, ch = w >> 2;
    const int b = blockIdx.y >> 3, h = blockIdx.y & 7;
    const int qt = blockIdx.x;

    const size_t sBN = (size_t)NN_ * HH_ * DD_;
    const float* qp = Qg + (size_t)b * sBN + (size_t)qt * 128 * 1024 + h * 128;
    const float* kp = Kg + (size_t)b * sBN + h * 128;
    const float* vp = Vt + (size_t)b * sBN + (size_t)(h * 128) * 1024;
    float*       cp = Cx + (size_t)b * sBN + (size_t)qt * 128 * 1024 + h * 128;

    // ---- stage Q ----
    {
        const int r  = w * 16 + gg + (s & 1) * 8;
        const int rm = s & 1;
        const float* src = qp + (size_t)r * 1024;
        #pragma unroll
        for (int i = 0; i < 16; i++) {
            const int qd = (s >> 1) + i * 2;
            uint4 v = *(const uint4*)(src + qd * 4);
            const uint32_t base =
                (uint32_t)((((w * 16 + (qd >> 1)) * 4 + (qd & 1) * 2 + rm) * 32) + gg * 4);
            *(uint4*)&sQ[base] = v;
        }
    }

    const float* kRow = kp + (size_t)(w * 8 + gg) * 1024;
    const int vdd = w * 16 + gg + (s & 1) * 8;
    const float* vRow = vp + (size_t)vdd * 1024;

    uint4 rK[8], rV[8];
    #pragma unroll
    for (int i = 0; i < 8; i++) {
        rK[i] = *(const uint4*)(kRow + (s + i * 4) * 4);
        rV[i] = *(const uint4*)(vRow + ((s >> 1) + i * 2) * 4);
    }

    float lp[2][2] = {};
    float o[2][8][4];
    #pragma unroll
    for (int mt = 0; mt < 2; mt++)
        #pragma unroll
        for (int nt = 0; nt < 8; nt++)
            #pragma unroll
            for (int r = 0; r < 4; r++) o[mt][nt][r] = 0.0f;

    for (int kt = 0; kt < 16; kt++) {
        __syncthreads();
        #pragma unroll
        for (int i = 0; i < 8; i++) {
            const int qd = s + i * 4;
            const uint32_t base =
                (uint32_t)(((((qd >> 1) * 8 + w) * 2 + (qd & 1)) * 32) + gg * 4);
            *(uint4*)&sK[base] = rK[i];
        }
        #pragma unroll
        for (int i = 0; i < 8; i++) {
            const int qd = (s >> 1) + i * 2;
            const uint32_t base =
                (uint32_t)(((((qd >> 1) * 16 + (vdd >> 3)) * 2 + (qd & 1)) * 32) + gg * 4);
            *(uint4*)&sV[base] = rV[i];
        }
        __syncthreads();

        if (kt + 1 < 16) {
            const float* kn = kRow + (size_t)(kt + 1) * 64 * 1024;
            const float* vn = vRow + (kt + 1) * 64;
            #pragma unroll
            for (int i = 0; i < 8; i++) {
                rK[i] = *(const uint4*)(kn + (s + i * 4) * 4);
                rV[i] = *(const uint4*)(vn + ((s >> 1) + i * 2) * 4);
            }
        }

        // ---- S = Qs @ K^T ----
        float sc[2][4][4];
        #pragma unroll
        for (int mt = 0; mt < 2; mt++)
            #pragma unroll
            for (int nt = 0; nt < 4; nt++)
                #pragma unroll
                for (int r = 0; r < 4; r++) sc[mt][nt][r] = 0.0f;
        #pragma unroll
        for (int kc = 0; kc < 16; kc++) {
            uint32_t af[2][4];
            #pragma unroll
            for (int mt = 0; mt < 2; mt++) {
                const uint32_t ab = (uint32_t)((((rg * 2 + mt) * 16 + kc) * 4) * 32 + l);
                af[mt][0] = sQ[ab];      af[mt][1] = sQ[ab + 32];
                af[mt][2] = sQ[ab + 64]; af[mt][3] = sQ[ab + 96];
            }
            #pragma unroll
            for (int nt = 0; nt < 4; nt++) {
                const uint32_t bb = (uint32_t)(((kc * 8 + ch * 4 + nt) * 2) * 32 + l);
                uint32_t bf[2] = {sK[bb], sK[bb + 32]};
                mma_tf32(sc[0][nt], af[0], bf);
                mma_tf32(sc[1][nt], af[1], bf);
            }
        }

        // ---- max-free softmax ----
        #pragma unroll
        for (int mt = 0; mt < 2; mt++) {
            #pragma unroll
            for (int nt = 0; nt < 4; nt++) {
                const float p0 = __expf(sc[mt][nt][0]);
                const float p1 = __expf(sc[mt][nt][1]);
                const float p2 = __expf(sc[mt][nt][2]);
                const float p3 = __expf(sc[mt][nt][3]);
                lp[mt][0] += p0 + p1;
                lp[mt][1] += p2 + p3;
                const uint32_t wb =
                    (uint32_t)((((rg * 2 + mt) * 8 + ch * 4 + nt) * 4 + (tig >> 1) * 2) * 32)
                    + g * 4 + (tig & 1) * 2;
                uint2 lo, hi;
                lo.x = tf32r(p0); lo.y = tf32r(p1);
                hi.x = tf32r(p2); hi.y = tf32r(p3);
                *(uint2*)&sP[wb]      = lo;
                *(uint2*)&sP[wb + 32] = hi;
            }
        }
        __syncthreads();

        // ---- O += P @ V ----
        #pragma unroll
        for (int kc = 0; kc < 8; kc++) {
            uint32_t af[2][4];
            #pragma unroll
            for (int mt = 0; mt < 2; mt++) {
                const uint32_t ab = (uint32_t)((((rg * 2 + mt) * 8 + kc) * 4) * 32 + l);
                af[mt][0] = sP[ab];      af[mt][1] = sP[ab + 32];
                af[mt][2] = sP[ab + 64]; af[mt][3] = sP[ab + 96];
            }
            #pragma unroll
            for (int nt = 0; nt < 8; nt++) {
                const uint32_t bb = (uint32_t)(((kc * 16 + ch * 8 + nt) * 2) * 32 + l);
                uint32_t bf[2] = {sV[bb], sV[bb + 32]};
                mma_tf32(o[0][nt], af[0], bf);
                mma_tf32(o[1][nt], af[1], bf);
            }
        }
    }

    // ---- combine l partials ----
    #pragma unroll
    for (int mt = 0; mt < 2; mt++)
        #pragma unroll
        for (int rm = 0; rm < 2; rm++) {
            lp[mt][rm] += __shfl_xor_sync(~0u, lp[mt][rm], 1);
            lp[mt][rm] += __shfl_xor_sync(~0u, lp[mt][rm], 2);
        }
    if (tig == 0) {
        lS[ch * 128 + rg * 32 + g]          = lp[0][0];
        lS[ch * 128 + rg * 32 + g + 8]      = lp[0][1];
        lS[ch * 128 + rg * 32 + 16 + g]     = lp[1][0];
        lS[ch * 128 + rg * 32 + 16 + g + 8] = lp[1][1];
    }
    __syncthreads();

    const float iA0 = 1.0f / (lS[rg * 32 + g]          + lS[128 + rg * 32 + g]);
    const float iA1 = 1.0f / (lS[rg * 32 + g + 8]      + lS[128 + rg * 32 + g + 8]);
    const float iB0 = 1.0f / (lS[rg * 32 + 16 + g]     + lS[128 + rg * 32 + 16 + g]);
    const float iB1 = 1.0f / (lS[rg * 32 + 16 + g + 8] + lS[128 + rg * 32 + 16 + g + 8]);
    float* r0p = cp + (size_t)(rg * 32 + g) * 1024;
    float* r1p = cp + (size_t)(rg * 32 + g + 8) * 1024;
    float* r2p = cp + (size_t)(rg * 32 + 16 + g) * 1024;
    float* r3p = cp + (size_t)(rg * 32 + 16 + g + 8) * 1024;
    #pragma unroll
    for (int nt = 0; nt < 8; nt++) {
        const int col = ch * 64 + nt * 8 + tig * 2;
        *(float2*)(r0p + col) = make_float2(o[0][nt][0] * iA0, o[0][nt][1] * iA0);
        *(float2*)(r1p + col) = make_float2(o[0][nt][2] * iA1, o[0][nt][3] * iA1);
        *(float2*)(r2p + col) = make_float2(o[1][nt][0] * iB0, o[1][nt][1] * iB0);
        *(float2*)(r3p + col) = make_float2(o[1][nt][2] * iB1, o[1][nt][3] * iB1);
    }
}

// ---------------------------------------------------------------------------
// tf32 GEMM (K templated): C = alpha*(A@B^T + bias) (+relu), opt C^T/tf32 out.
// SYM: blockIdx.x encodes upper-triangle block pair of an 8x8 grid; mirrors.
// ---------------------------------------------------------------------------
template<bool RELU, bool HASBIAS, bool CT, bool TF32OUT, int KT, bool SYM>
__global__ void __launch_bounds__(256)
gemm_tb(const float* __restrict__ A, int lda, size_t aOut, size_t aIn,
        const float* __restrict__ B, int ldb, size_t bOut, size_t bIn,
        float*       __restrict__ C, int ldc, size_t cOut, size_t cIn,
        const float* __restrict__ bias,
        int zInner, float alpha) {
    __shared__ uint32_t sA[2][2048];
    __shared__ uint32_t sB[2][2048];

    const int tid  = threadIdx.x;
    const int wid  = tid >> 5;
    const int lane = tid & 31;
    const int warp_m = wid & 3;
    const int warp_n = wid >> 2;
    const int g   = lane >> 2;
    const int tig = lane & 3;

    int z  = blockIdx.z;
    int zo = z / zInner, zi = z - zo * zInner;
    A += (size_t)zo * aOut + (size_t)zi * aIn;
    B += (size_t)zo * bOut + (size_t)zi * bIn;
    C += (size_t)zo * cOut + (size_t)zi * cIn;

    int xb = blockIdx.x, yb = blockIdx.y;
    if (SYM) {
        int idx = blockIdx.x, y = 0;
        while (idx >= 8 - y) { idx -= 8 - y; y++; }
        yb = y; xb = y + idx;
    }
    const int m0 = yb * 128, n0 = xb * 128;

    const int sw = wid;
    const int qk = lane >> 3;
    const int gg = lane & 7;
    const int rk = qk & 1, kk0 = qk >> 1;

    const uint32_t aSt0 = ((((((sw >> 1) * 2 + kk0) * 2) + (sw & 1)) * 4 + rk * 2) * 32) + gg * 4;
    const uint32_t aSt1 = aSt0 + 32;
    const uint32_t bSt0 = (((((sw >> 2) * 2 + kk0) * 8 + ((sw * 2) & 7)) * 2 + rk) * 32) + gg * 4;
    const uint32_t bSt1 = bSt0 + 64;

    const float* Ap = A + (size_t)(m0 + sw * 16 + gg) * lda + qk * 4;
    const float* Bp = B + (size_t)(n0 + sw * 16 + gg) * ldb + qk * 4;
    const size_t a8 = (size_t)8 * lda, b8 = (size_t)8 * ldb;

    float acc[2][8][4];
    #pragma unroll
    for (int mt = 0; mt < 2; mt++)
        #pragma unroll
        for (int nt = 0; nt < 8; nt++)
            #pragma unroll
            for (int r = 0; r < 4; r++) acc[mt][nt][r] = 0.0f;

    float4 ra0, ra1, rb0, rb1;
    ra0 = *(const float4*)(Ap);
    ra1 = *(const float4*)(Ap + a8);
    rb0 = *(const float4*)(Bp);
    rb1 = *(const float4*)(Bp + b8);
    *(uint4*)&sA[0][aSt0] = cvt4(ra0);
    *(uint4*)&sA[0][aSt1] = cvt4(ra1);
    *(uint4*)&sB[0][bSt0] = cvt4(rb0);
    *(uint4*)&sB[0][bSt1] = cvt4(rb1);
    __syncthreads();

    constexpr int nkt = KT >> 4;
    #pragma unroll 4
    for (int kt = 0; kt < nkt; kt++) {
        const int cur = kt & 1;
        if (kt + 1 < nkt) {
            const int k0 = (kt + 1) << 4;
            ra0 = *(const float4*)(Ap + k0);
            ra1 = *(const float4*)(Ap + k0 + a8);
            rb0 = *(const float4*)(Bp + k0);
            rb1 = *(const float4*)(Bp + k0 + b8);
        }
        const uint32_t* aB = sA[cur];
        const uint32_t* bB = sB[cur];
        #pragma unroll
        for (int kk = 0; kk < 2; kk++) {
            uint32_t af[2][4];
            #pragma unroll
            for (int mt = 0; mt < 2; mt++) {
                const uint32_t base = (((warp_m * 2 + kk) * 2 + mt) * 4) * 32 + lane;
                af[mt][0] = aB[base];
                af[mt][1] = aB[base + 32];
                af[mt][2] = aB[base + 64];
                af[mt][3] = aB[base + 96];
            }
            uint32_t bf[8][2];
            #pragma unroll
            for (int nt = 0; nt < 8; nt++) {
                const uint32_t base = ((((warp_n * 2 + kk) * 8 + nt) * 2) * 32) + lane;
                bf[nt][0] = bB[base];
                bf[nt][1] = bB[base + 32];
            }
            #pragma unroll
            for (int mt = 0; mt < 2; mt++)
                #pragma unroll
                for (int nt = 0; nt < 8; nt++)
                    mma_tf32(acc[mt][nt], af[mt], bf[nt]);
        }
        if (kt + 1 < nkt) {
            const int nxt = cur ^ 1;
            __syncthreads();
            *(uint4*)&sA[nxt][aSt0] = cvt4(ra0);
            *(uint4*)&sA[nxt][aSt1] = cvt4(ra1);
            *(uint4*)&sB[nxt][bSt0] = cvt4(rb0);
            *(uint4*)&sB[nxt][bSt1] = cvt4(rb1);
            __syncthreads();
        }
    }

    #pragma unroll
    for (int mt = 0; mt < 2; mt++) {
        const int row = m0 + warp_m * 32 + mt * 16 + g;
        #pragma unroll
        for (int nt = 0; nt < 8; nt++) {
            const int col = n0 + warp_n * 64 + nt * 8 + tig * 2;
            float v0 = acc[mt][nt][0];
            float v1 = acc[mt][nt][1];
            float v2 = acc[mt][nt][2];
            float v3 = acc[mt][nt][3];
            if (HASBIAS) {
                float b0 = bias[col], b1 = bias[col + 1];
                v0 += b0; v1 += b1; v2 += b0; v3 += b1;
            }
            v0 *= alpha; v1 *= alpha; v2 *= alpha; v3 *= alpha;
            if (RELU) {
                v0 = fmaxf(v0, 0.0f); v1 = fmaxf(v1, 0.0f);
                v2 = fmaxf(v2, 0.0f); v3 = fmaxf(v3, 0.0f);
            }
            if (TF32OUT) {
                v0 = __uint_as_float(tf32r(v0));
                v1 = __uint_as_float(tf32r(v1));
                v2 = __uint_as_float(tf32r(v2));
                v3 = __uint_as_float(tf32r(v3));
            }
            if (CT) {
                C[(size_t)col * ldc + row]           = v0;
                C[(size_t)(col + 1) * ldc + row]     = v1;
                C[(size_t)col * ldc + row + 8]       = v2;
                C[(size_t)(col + 1) * ldc + row + 8] = v3;
            } else {
                *(float2*)(C + (size_t)row * ldc + col)       = make_float2(v0, v1);
                *(float2*)(C + (size_t)(row + 8) * ldc + col) = make_float2(v2, v3);
                if (SYM && xb != yb) {
                    C[(size_t)col * ldc + row]           = v0;
                    C[(size_t)(col + 1) * ldc + row]     = v1;
                    C[(size_t)col * ldc + row + 8]       = v2;
                    C[(size_t)(col + 1) * ldc + row + 8] = v3;
                }
            }
        }
    }
}

// ---------------------------------------------------------------------------
__global__ void k_transpose3(const float* __restrict__ i0, float* __restrict__ o0,
                             const float* __restrict__ i1, float* __restrict__ o1,
                             const float* __restrict__ i2, float* __restrict__ o2) {
    __shared__ float t[32][33];
    const float* in = (blockIdx.z == 0) ? i0 : (blockIdx.z == 1) ? i1 : i2;
    float* out      = (blockIdx.z == 0) ? o0 : (blockIdx.z == 1) ? o1 : o2;
    const int C = HH_ * DD_, R = DD_;
    int bx = blockIdx.x * 32, by = blockIdx.y * 32;
    #pragma unroll
    for (int i = 0; i < 32; i += 8)
        t[threadIdx.y + i][threadIdx.x] = in[(size_t)(by + threadIdx.y + i) * C + bx + threadIdx.x];
    __syncthreads();
    #pragma unroll
    for (int i = 0; i < 32; i += 8)
        out[(size_t)(bx + threadIdx.y + i) * R + by + threadIdx.x] = t[threadIdx.x][threadIdx.y + i];
}

// ---------------------------------------------------------------------------
// Merged Wg prep: blocks (0..3, y) transpose Wg [128,128] -> wgT;
// block (4, 0) computes b2 = bo @ Wg.  grid (5,4), block (32,8).
// ---------------------------------------------------------------------------
__global__ void k_prepWg(const float* __restrict__ Wg, float* __restrict__ wgT,
                         const float* __restrict__ bo, float* __restrict__ b2) {
    if (blockIdx.x < 4) {
        __shared__ float t[32][33];
        int bx = blockIdx.x * 32, by = blockIdx.y * 32;
        #pragma unroll
        for (int i = 0; i < 32; i += 8)
            t[threadIdx.y + i][threadIdx.x] = Wg[(size_t)(by + threadIdx.y + i) * DD_ + bx + threadIdx.x];
        __syncthreads();
        #pragma unroll
        for (int i = 0; i < 32; i += 8)
            wgT[(size_t)(bx + threadIdx.y + i) * DD_ + by + threadIdx.x] = t[threadIdx.x][threadIdx.y + i];
    } else if (blockIdx.y == 0) {
        int j = threadIdx.y * 32 + threadIdx.x;
        if (j < DD_) {
            float s = 0.0f;
            for (int k = 0; k < DD_; k++) s += bo[k] * Wg[k * DD_ + j];
            b2[j] = s;
        }
    }
}

// ---------------------------------------------------------------------------
__global__ void k_embed_add(const float* __restrict__ F_c,
                            const int*   __restrict__ t,
                            float*       __restrict__ c) {
    int bn = blockIdx.x;
    int b  = bn >> 10;
    int n  = bn & 1023;
    float tv = (float)t[b];
    const float kC = logf(1000.0f) / 511.0f;
    int   i = (n < 512) ? n : (n - 512);
    float f = __expf(-(float)i * kC);
    float e = tv * f;
    float emb = (n < 512) ? sinf(e) : cosf(e);
    size_t base = (size_t)bn * DD_;
    int d = threadIdx.x;
    c[base + d] = F_c[base + d] + emb;
}

// ---------------------------------------------------------------------------
__global__ void k_rownorm(const float* __restrict__ feat,
                          float*       __restrict__ out) {
    int tid = threadIdx.x;
    size_t base = (size_t)blockIdx.x * DD_;
    float x = feat[base + tid];
    __shared__ float red[4];
    float s = x;
    #pragma unroll
    for (int o = 16; o > 0; o >>= 1) s += __shfl_xor_sync(0xffffffffu, s, o);
    if ((tid & 31) == 0) red[tid >> 5] = s;
    __syncthreads();
    float mu = (red[0] + red[1] + red[2] + red[3]) * (1.0f / 128.0f);
    float d = x - mu;
    float ss = d * d;
    #pragma unroll
    for (int o = 16; o > 0; o >>= 1) ss += __shfl_xor_sync(0xffffffffu, ss, o);
    __syncthreads();
    if ((tid & 31) == 0) red[tid >> 5] = ss;
    __syncthreads();
    float var = (red[0] + red[1] + red[2] + red[3]) * (1.0f / 127.0f);
    float inv = 1.0f / (sqrtf(var) + 1e-8f);
    out[base + tid] = d * inv;
}

// ---------------------------------------------------------------------------
extern "C" void kernel_launch(void* const* d_in, const int* in_sizes, int n_in,
                              void* d_out, int out_size) {
    const float* A_t = (const float*)d_in[0];
    const float* F_c = (const float*)d_in[1];
    const int*   t   = (const int*)  d_in[2];
    const float* Wq  = (const float*)d_in[3];
    const float* bq  = (const float*)d_in[4];
    const float* Wk  = (const float*)d_in[5];
    const float* bk  = (const float*)d_in[6];
    const float* Wv  = (const float*)d_in[7];
    const float* bv  = (const float*)d_in[8];
    const float* Wo  = (const float*)d_in[9];
    const float* bo  = (const float*)d_in[10];
    const float* Wg  = (const float*)d_in[11];
    float* out = (float*)d_out;

    float *c, *q, *k, *vt, *ctx, *hwt, *feat, *nrm;
    float *wqT, *wkT, *wvT, *w2T, *wgT, *b2;
    cudaGetSymbolAddress((void**)&c,    g_c);
    cudaGetSymbolAddress((void**)&q,    g_q);
    cudaGetSymbolAddress((void**)&k,    g_k);
    cudaGetSymbolAddress((void**)&vt,   g_vt);
    cudaGetSymbolAddress((void**)&ctx,  g_ctx);
    cudaGetSymbolAddress((void**)&hwt,  g_hwt);
    cudaGetSymbolAddress((void**)&feat, g_feat);
    cudaGetSymbolAddress((void**)&nrm,  g_norm);
    cudaGetSymbolAddress((void**)&wqT,  g_wqT);
    cudaGetSymbolAddress((void**)&wkT,  g_wkT);
    cudaGetSymbolAddress((void**)&wvT,  g_wvT);
    cudaGetSymbolAddress((void**)&w2T,  g_w2T);
    cudaGetSymbolAddress((void**)&wgT,  g_wgT);
    cudaGetSymbolAddress((void**)&b2,   g_b2);

    const size_t sBN = (size_t)NN_ * HH_ * DD_;
    const size_t sBD = (size_t)NN_ * DD_;
    const size_t sNN = (size_t)NN_ * NN_;
    const int    HD  = HH_ * DD_;
    const float  scl = 0.08838834764831845f;    // 1/sqrt(128)
    const int    FLASH_SMEM = 40960 * 4 + 1024;

    cudaFuncSetAttribute(k_flash, cudaFuncAttributeMaxDynamicSharedMemorySize, FLASH_SMEM);

    // (1) QKV weight transposes
    k_transpose3<<<dim3(32, 4, 3), dim3(32, 8)>>>(Wq, wqT, Wk, wkT, Wv, wvT);

    // (2) c = F_c + t_emb
    k_embed_add<<<BSZ * NN_, DD_>>>(F_c, t, c);

    // (3-5) QKV GEMMs (tf32-rounded outputs; Q pre-scaled)
    {
        dim3 g(8, 8, BSZ);
        gemm_tb<false, true, false, true, 128, false><<<g, 256>>>(c, DD_, sBD, 0,
                                                                  wqT, DD_, 0, 0,
                                                                  q, HD, sBN, 0,
                                                                  bq, 1, scl);
        gemm_tb<false, true, false, true, 128, false><<<g, 256>>>(c, DD_, sBD, 0,
                                                                  wkT, DD_, 0, 0,
                                                                  k, HD, sBN, 0,
                                                                  bk, 1, 1.0f);
        gemm_tb<false, true, true, true, 128, false><<<g, 256>>>(c, DD_, sBD, 0,
                                                                 wvT, DD_, 0, 0,
                                                                 vt, NN_, sBN, 0,
                                                                 bv, 1, 1.0f);
    }

    // (6) fused attention
    k_flash<<<dim3(8, BSZ * HH_), 256, FLASH_SMEM>>>(q, k, vt, ctx);

    // (7-8) merged Wo+Wg prep (transpose + bias2 in one launch, then W2T)
    k_prepWg<<<dim3(5, 4), dim3(32, 8)>>>(Wg, wgT, bo, b2);
    gemm_tb<false, false, false, false, 128, false><<<dim3(8, 1, 1), 256>>>(
        wgT, DD_, 0, 0, Wo, DD_, 0, 0, w2T, NN_, 0, 0,
        nullptr, 1, 1.0f);

    // (9) hwt = (ctx @ W2 + b2)^T
    {
        dim3 g(1, 8, BSZ);
        gemm_tb<false, true, true, false, 1024, false><<<g, 256>>>(ctx, HD, sBN, 0,
                                                                   w2T, NN_, 0, 0,
                                                                   hwt, NN_, sBD, 0,
                                                                   b2, 1, 1.0f);
    }
    // (10) feat = relu(A_t @ hw)
    {
        dim3 g(1, 8, BSZ);
        gemm_tb<true, false, false, false, 1024, false><<<g, 256>>>(A_t, NN_, sNN, 0,
                                                                    hwt, NN_, sBD, 0,
                                                                    feat, DD_, sBD, 0,
                                                                    nullptr, 1, 1.0f);
    }
    // (11) row normalize
    k_rownorm<<<BSZ * NN_, DD_>>>(feat, nrm);

    // (12) out = (norm @ norm^T) / 128  — symmetric blocks, mirrored
    {
        dim3 g(36, 1, BSZ);
        gemm_tb<false, false, false, false, 128, true><<<g, 256>>>(nrm, DD_, sBD, 0,
                                                                   nrm, DD_, sBD, 0,
                                                                   out, NN_, sNN, 0,
                                                                   nullptr, 1, 1.0f / 128.0f);
    }
}

// round 17
// speedup vs baseline: 1.3283x; 1.0433x over previous
#include <cuda_runtime.h>
#include <math.h>
#include <stdint.h>

#define BSZ 16
#define NN_ 1024
#define DD_ 128
#define HH_ 8

// ---------------------------------------------------------------------------
// Static scratch
// ---------------------------------------------------------------------------
__device__ float g_c   [BSZ * NN_ * DD_];
__device__ float g_q   [BSZ * NN_ * HH_ * DD_];      // [b,n,hd] tf32, pre-scaled
__device__ float g_k   [BSZ * NN_ * HH_ * DD_];      // [b,n,hd] tf32
__device__ float g_vt  [BSZ * NN_ * HH_ * DD_];      // [b,hd,n] tf32 (V^T)
__device__ float g_ctx [BSZ * NN_ * HH_ * DD_];      // [b,n,hd]
__device__ float g_hwt [BSZ * NN_ * DD_];            // [b,d,n]  (hw^T)
__device__ float g_feat[BSZ * NN_ * DD_];
__device__ float g_norm[BSZ * NN_ * DD_];
__device__ float g_wqT [NN_ * DD_];
__device__ float g_wkT [NN_ * DD_];
__device__ float g_wvT [NN_ * DD_];
__device__ float g_w2T [DD_ * NN_];
__device__ float g_wgT [DD_ * DD_];
__device__ float g_b2  [DD_];

// ---------------------------------------------------------------------------
__device__ __forceinline__ uint32_t tf32r(float x) {
    uint32_t u;
    asm("cvt.rna.tf32.f32 %0, %1;" : "=r"(u) : "f"(x));
    return u;
}
__device__ __forceinline__ void mma_tf32(float* d, const uint32_t* a, const uint32_t* b) {
    asm volatile(
        "mma.sync.aligned.m16n8k8.row.col.f32.tf32.tf32.f32 "
        "{%0,%1,%2,%3}, {%4,%5,%6,%7}, {%8,%9}, {%0,%1,%2,%3};"
        : "+f"(d[0]), "+f"(d[1]), "+f"(d[2]), "+f"(d[3])
        : "r"(a[0]), "r"(a[1]), "r"(a[2]), "r"(a[3]), "r"(b[0]), "r"(b[1]));
}
__device__ __forceinline__ uint4 cvt4(float4 v) {
    uint4 u;
    u.x = tf32r(v.x); u.y = tf32r(v.y); u.z = tf32r(v.z); u.w = tf32r(v.w);
    return u;
}

// ---------------------------------------------------------------------------
// Fused flash attention, 2 q-tiles per CTA, K-tile 32, max-free softmax.
// smem (words): sQ 2x16384, sK 4096, sV 4096, sP 2x4096, lS 512.
// QK: warp (rg=w&3, ch=w>>2): rows rg*32..+32 x key-cols ch*16..+16 (per qh).
// PV: warp (rg, ch): rows rg*32..+32 x d-cols ch*64..+64 (per qh).
// 3 __syncthreads per K-tile serving BOTH q-tiles.
// ---------------------------------------------------------------------------
__global__ void __launch_bounds__(256) k_flash(
    const float* __restrict__ Qg, const float* __restrict__ Kg,
    const float* __restrict__ Vt, float* __restrict__ Cx) {
    extern __shared__ uint32_t dsm[];
    uint32_t* sQ  = dsm;                 // 2 x 16384
    uint32_t* sK  = dsm + 32768;         // 4096
    uint32_t* sV  = dsm + 36864;         // 4096
    uint32_t* sP  = dsm + 40960;         // 2 x 4096
    float*    lS  = (float*)(dsm + 49152); // 512 floats: [qh][ch][row128]

    const int tid = threadIdx.x;
    const int w = tid >> 5, l = tid & 31;
    const int g = l >> 2, tig = l & 3;
    const int gg = l & 7, s = l >> 3;
    const int rg = w & 3, ch = w >> 2;
    const int b = blockIdx.y >> 3, h = blockIdx.y & 7;
    const int qt = blockIdx.x;           // 0..3 (256 rows each)

    const size_t sBN = (size_t)NN_ * HH_ * DD_;
    const float* qp = Qg + (size_t)b * sBN + (size_t)qt * 256 * 1024 + h * 128;
    const float* kp = Kg + (size_t)b * sBN + h * 128;
    const float* vp = Vt + (size_t)b * sBN + (size_t)(h * 128) * 1024;
    float*       cp = Cx + (size_t)b * sBN + (size_t)qt * 256 * 1024 + h * 128;

    // ---- stage Q (both halves; raw bit copy, already tf32 + scaled) ----
    #pragma unroll
    for (int qh = 0; qh < 2; qh++) {
        const int r  = w * 16 + gg + (s & 1) * 8;
        const int rm = s & 1;
        const float* src = qp + (size_t)(qh * 128 + r) * 1024;
        uint32_t* sQh = sQ + qh * 16384;
        #pragma unroll
        for (int i = 0; i < 16; i++) {
            const int qd = (s >> 1) + i * 2;
            uint4 v = *(const uint4*)(src + qd * 4);
            const uint32_t base =
                (uint32_t)((((w * 16 + (qd >> 1)) * 4 + (qd & 1) * 2 + rm) * 32) + gg * 4);
            *(uint4*)&sQh[base] = v;
        }
    }

    // ---- K/V staging coordinates (K-tile = 32 keys) ----
    const int krow = (w & 3) * 8 + gg;               // 0..31
    const int kq0  = (w >> 2) * 16 + s;              // first quad (of 32)
    const float* kRow = kp + (size_t)krow * 1024 + kq0 * 4;
    const int vdd = w * 16 + gg + (s & 1) * 8;       // 0..127
    const int vq0 = s >> 1;                          // first quad (of 8)
    const float* vRow = vp + (size_t)vdd * 1024 + vq0 * 4;

    uint32_t kOff[4], vOff[4];
    #pragma unroll
    for (int i = 0; i < 4; i++) {
        const int qd = kq0 + i * 4;
        kOff[i] = (uint32_t)(((((qd >> 1) * 4 + (krow >> 3)) * 2 + (qd & 1)) * 32) + gg * 4);
        const int qv = vq0 + i * 2;
        vOff[i] = (uint32_t)(((((qv >> 1) * 16 + (vdd >> 3)) * 2 + (qv & 1)) * 32) + gg * 4);
    }

    uint4 rK[4], rV[4];
    #pragma unroll
    for (int i = 0; i < 4; i++) {
        rK[i] = *(const uint4*)(kRow + i * 16);
        rV[i] = *(const uint4*)(vRow + i * 8);
    }

    float lp[2][2][2] = {};
    float o[2][2][8][4];
    #pragma unroll
    for (int qh = 0; qh < 2; qh++)
        #pragma unroll
        for (int mt = 0; mt < 2; mt++)
            #pragma unroll
            for (int nt = 0; nt < 8; nt++)
                #pragma unroll
                for (int r = 0; r < 4; r++) o[qh][mt][nt][r] = 0.0f;

    for (int kt = 0; kt < 32; kt++) {
        __syncthreads();   // prior PV reads of sK/sV/sP done; iter0: Q staged
        #pragma unroll
        for (int i = 0; i < 4; i++) *(uint4*)&sK[kOff[i]] = rK[i];
        #pragma unroll
        for (int i = 0; i < 4; i++) *(uint4*)&sV[vOff[i]] = rV[i];
        __syncthreads();

        if (kt + 1 < 32) {
            const float* kn = kRow + (size_t)(kt + 1) * 32 * 1024;
            const float* vn = vRow + (kt + 1) * 32;
            #pragma unroll
            for (int i = 0; i < 4; i++) {
                rK[i] = *(const uint4*)(kn + i * 16);
                rV[i] = *(const uint4*)(vn + i * 8);
            }
        }

        // ---- QK + softmax for both q-tiles ----
        #pragma unroll
        for (int qh = 0; qh < 2; qh++) {
            const uint32_t* sQh = sQ + qh * 16384;
            uint32_t* sPh = sP + qh * 4096;
            float sc[2][2][4];
            #pragma unroll
            for (int mt = 0; mt < 2; mt++)
                #pragma unroll
                for (int nt = 0; nt < 2; nt++)
                    #pragma unroll
                    for (int r = 0; r < 4; r++) sc[mt][nt][r] = 0.0f;
            #pragma unroll
            for (int kc = 0; kc < 16; kc++) {
                uint32_t af[2][4];
                #pragma unroll
                for (int mt = 0; mt < 2; mt++) {
                    const uint32_t ab = (uint32_t)((((rg * 2 + mt) * 16 + kc) * 4) * 32 + l);
                    af[mt][0] = sQh[ab];      af[mt][1] = sQh[ab + 32];
                    af[mt][2] = sQh[ab + 64]; af[mt][3] = sQh[ab + 96];
                }
                #pragma unroll
                for (int nt = 0; nt < 2; nt++) {
                    const uint32_t bb = (uint32_t)(((kc * 4 + ch * 2 + nt) * 2) * 32 + l);
                    uint32_t bf[2] = {sK[bb], sK[bb + 32]};
                    mma_tf32(sc[0][nt], af[0], bf);
                    mma_tf32(sc[1][nt], af[1], bf);
                }
            }
            #pragma unroll
            for (int mt = 0; mt < 2; mt++) {
                #pragma unroll
                for (int nt = 0; nt < 2; nt++) {
                    const float p0 = __expf(sc[mt][nt][0]);
                    const float p1 = __expf(sc[mt][nt][1]);
                    const float p2 = __expf(sc[mt][nt][2]);
                    const float p3 = __expf(sc[mt][nt][3]);
                    lp[qh][mt][0] += p0 + p1;
                    lp[qh][mt][1] += p2 + p3;
                    const uint32_t wb =
                        (uint32_t)((((rg * 2 + mt) * 4 + ch * 2 + nt) * 4 + (tig >> 1) * 2) * 32)
                        + g * 4 + (tig & 1) * 2;
                    uint2 lo, hi;
                    lo.x = tf32r(p0); lo.y = tf32r(p1);
                    hi.x = tf32r(p2); hi.y = tf32r(p3);
                    *(uint2*)&sPh[wb]      = lo;
                    *(uint2*)&sPh[wb + 32] = hi;
                }
            }
        }
        __syncthreads();

        // ---- PV for both q-tiles ----
        #pragma unroll
        for (int qh = 0; qh < 2; qh++) {
            const uint32_t* sPh = sP + qh * 4096;
            #pragma unroll
            for (int kc = 0; kc < 4; kc++) {
                uint32_t af[2][4];
                #pragma unroll
                for (int mt = 0; mt < 2; mt++) {
                    const uint32_t ab = (uint32_t)((((rg * 2 + mt) * 4 + kc) * 4) * 32 + l);
                    af[mt][0] = sPh[ab];      af[mt][1] = sPh[ab + 32];
                    af[mt][2] = sPh[ab + 64]; af[mt][3] = sPh[ab + 96];
                }
                #pragma unroll
                for (int nt = 0; nt < 8; nt++) {
                    const uint32_t bb = (uint32_t)(((kc * 16 + ch * 8 + nt) * 2) * 32 + l);
                    uint32_t bf[2] = {sV[bb], sV[bb + 32]};
                    mma_tf32(o[qh][0][nt], af[0], bf);
                    mma_tf32(o[qh][1][nt], af[1], bf);
                }
            }
        }
    }

    // ---- combine l partials across column halves ----
    #pragma unroll
    for (int qh = 0; qh < 2; qh++)
        #pragma unroll
        for (int mt = 0; mt < 2; mt++)
            #pragma unroll
            for (int rm = 0; rm < 2; rm++) {
                lp[qh][mt][rm] += __shfl_xor_sync(~0u, lp[qh][mt][rm], 1);
                lp[qh][mt][rm] += __shfl_xor_sync(~0u, lp[qh][mt][rm], 2);
            }
    if (tig == 0) {
        #pragma unroll
        for (int qh = 0; qh < 2; qh++) {
            float* d = lS + qh * 256 + ch * 128 + rg * 32;
            d[g]          = lp[qh][0][0];
            d[g + 8]      = lp[qh][0][1];
            d[16 + g]     = lp[qh][1][0];
            d[16 + g + 8] = lp[qh][1][1];
        }
    }
    __syncthreads();

    #pragma unroll
    for (int qh = 0; qh < 2; qh++) {
        const float* l0 = lS + qh * 256 + rg * 32;
        const float* l1 = lS + qh * 256 + 128 + rg * 32;
        const float iA0 = 1.0f / (l0[g]          + l1[g]);
        const float iA1 = 1.0f / (l0[g + 8]      + l1[g + 8]);
        const float iB0 = 1.0f / (l0[16 + g]     + l1[16 + g]);
        const float iB1 = 1.0f / (l0[16 + g + 8] + l1[16 + g + 8]);
        float* base = cp + (size_t)(qh * 128 + rg * 32) * 1024;
        float* r0p = base + (size_t)g * 1024;
        float* r1p = base + (size_t)(g + 8) * 1024;
        float* r2p = base + (size_t)(16 + g) * 1024;
        float* r3p = base + (size_t)(16 + g + 8) * 1024;
        #pragma unroll
        for (int nt = 0; nt < 8; nt++) {
            const int col = ch * 64 + nt * 8 + tig * 2;
            *(float2*)(r0p + col) = make_float2(o[qh][0][nt][0] * iA0, o[qh][0][nt][1] * iA0);
            *(float2*)(r1p + col) = make_float2(o[qh][0][nt][2] * iA1, o[qh][0][nt][3] * iA1);
            *(float2*)(r2p + col) = make_float2(o[qh][1][nt][0] * iB0, o[qh][1][nt][1] * iB0);
            *(float2*)(r3p + col) = make_float2(o[qh][1][nt][2] * iB1, o[qh][1][nt][3] * iB1);
        }
    }
}

// ---------------------------------------------------------------------------
// tf32 GEMM (K templated): C = alpha*(A@B^T + bias) (+relu), opt C^T/tf32 out.
// SYM: blockIdx.x encodes upper-triangle block pair of an 8x8 grid; mirrors.
// ---------------------------------------------------------------------------
template<bool RELU, bool HASBIAS, bool CT, bool TF32OUT, int KT, bool SYM>
__global__ void __launch_bounds__(256)
gemm_tb(const float* __restrict__ A, int lda, size_t aOut, size_t aIn,
        const float* __restrict__ B, int ldb, size_t bOut, size_t bIn,
        float*       __restrict__ C, int ldc, size_t cOut, size_t cIn,
        const float* __restrict__ bias,
        int zInner, float alpha) {
    __shared__ uint32_t sA[2][2048];
    __shared__ uint32_t sB[2][2048];

    const int tid  = threadIdx.x;
    const int wid  = tid >> 5;
    const int lane = tid & 31;
    const int warp_m = wid & 3;
    const int warp_n = wid >> 2;
    const int g   = lane >> 2;
    const int tig = lane & 3;

    int z  = blockIdx.z;
    int zo = z / zInner, zi = z - zo * zInner;
    A += (size_t)zo * aOut + (size_t)zi * aIn;
    B += (size_t)zo * bOut + (size_t)zi * bIn;
    C += (size_t)zo * cOut + (size_t)zi * cIn;

    int xb = blockIdx.x, yb = blockIdx.y;
    if (SYM) {
        int idx = blockIdx.x, y = 0;
        while (idx >= 8 - y) { idx -= 8 - y; y++; }
        yb = y; xb = y + idx;
    }
    const int m0 = yb * 128, n0 = xb * 128;

    const int sw = wid;
    const int qk = lane >> 3;
    const int gg = lane & 7;
    const int rk = qk & 1, kk0 = qk >> 1;

    const uint32_t aSt0 = ((((((sw >> 1) * 2 + kk0) * 2) + (sw & 1)) * 4 + rk * 2) * 32) + gg * 4;
    const uint32_t aSt1 = aSt0 + 32;
    const uint32_t bSt0 = (((((sw >> 2) * 2 + kk0) * 8 + ((sw * 2) & 7)) * 2 + rk) * 32) + gg * 4;
    const uint32_t bSt1 = bSt0 + 64;

    const float* Ap = A + (size_t)(m0 + sw * 16 + gg) * lda + qk * 4;
    const float* Bp = B + (size_t)(n0 + sw * 16 + gg) * ldb + qk * 4;
    const size_t a8 = (size_t)8 * lda, b8 = (size_t)8 * ldb;

    float acc[2][8][4];
    #pragma unroll
    for (int mt = 0; mt < 2; mt++)
        #pragma unroll
        for (int nt = 0; nt < 8; nt++)
            #pragma unroll
            for (int r = 0; r < 4; r++) acc[mt][nt][r] = 0.0f;

    float4 ra0, ra1, rb0, rb1;
    ra0 = *(const float4*)(Ap);
    ra1 = *(const float4*)(Ap + a8);
    rb0 = *(const float4*)(Bp);
    rb1 = *(const float4*)(Bp + b8);
    *(uint4*)&sA[0][aSt0] = cvt4(ra0);
    *(uint4*)&sA[0][aSt1] = cvt4(ra1);
    *(uint4*)&sB[0][bSt0] = cvt4(rb0);
    *(uint4*)&sB[0][bSt1] = cvt4(rb1);
    __syncthreads();

    constexpr int nkt = KT >> 4;
    #pragma unroll 4
    for (int kt = 0; kt < nkt; kt++) {
        const int cur = kt & 1;
        if (kt + 1 < nkt) {
            const int k0 = (kt + 1) << 4;
            ra0 = *(const float4*)(Ap + k0);
            ra1 = *(const float4*)(Ap + k0 + a8);
            rb0 = *(const float4*)(Bp + k0);
            rb1 = *(const float4*)(Bp + k0 + b8);
        }
        const uint32_t* aB = sA[cur];
        const uint32_t* bB = sB[cur];
        #pragma unroll
        for (int kk = 0; kk < 2; kk++) {
            uint32_t af[2][4];
            #pragma unroll
            for (int mt = 0; mt < 2; mt++) {
                const uint32_t base = (((warp_m * 2 + kk) * 2 + mt) * 4) * 32 + lane;
                af[mt][0] = aB[base];
                af[mt][1] = aB[base + 32];
                af[mt][2] = aB[base + 64];
                af[mt][3] = aB[base + 96];
            }
            uint32_t bf[8][2];
            #pragma unroll
            for (int nt = 0; nt < 8; nt++) {
                const uint32_t base = ((((warp_n * 2 + kk) * 8 + nt) * 2) * 32) + lane;
                bf[nt][0] = bB[base];
                bf[nt][1] = bB[base + 32];
            }
            #pragma unroll
            for (int mt = 0; mt < 2; mt++)
                #pragma unroll
                for (int nt = 0; nt < 8; nt++)
                    mma_tf32(acc[mt][nt], af[mt], bf[nt]);
        }
        if (kt + 1 < nkt) {
            const int nxt = cur ^ 1;
            __syncthreads();
            *(uint4*)&sA[nxt][aSt0] = cvt4(ra0);
            *(uint4*)&sA[nxt][aSt1] = cvt4(ra1);
            *(uint4*)&sB[nxt][bSt0] = cvt4(rb0);
            *(uint4*)&sB[nxt][bSt1] = cvt4(rb1);
            __syncthreads();
        }
    }

    #pragma unroll
    for (int mt = 0; mt < 2; mt++) {
        const int row = m0 + warp_m * 32 + mt * 16 + g;
        #pragma unroll
        for (int nt = 0; nt < 8; nt++) {
            const int col = n0 + warp_n * 64 + nt * 8 + tig * 2;
            float v0 = acc[mt][nt][0];
            float v1 = acc[mt][nt][1];
            float v2 = acc[mt][nt][2];
            float v3 = acc[mt][nt][3];
            if (HASBIAS) {
                float b0 = bias[col], b1 = bias[col + 1];
                v0 += b0; v1 += b1; v2 += b0; v3 += b1;
            }
            v0 *= alpha; v1 *= alpha; v2 *= alpha; v3 *= alpha;
            if (RELU) {
                v0 = fmaxf(v0, 0.0f); v1 = fmaxf(v1, 0.0f);
                v2 = fmaxf(v2, 0.0f); v3 = fmaxf(v3, 0.0f);
            }
            if (TF32OUT) {
                v0 = __uint_as_float(tf32r(v0));
                v1 = __uint_as_float(tf32r(v1));
                v2 = __uint_as_float(tf32r(v2));
                v3 = __uint_as_float(tf32r(v3));
            }
            if (CT) {
                C[(size_t)col * ldc + row]           = v0;
                C[(size_t)(col + 1) * ldc + row]     = v1;
                C[(size_t)col * ldc + row + 8]       = v2;
                C[(size_t)(col + 1) * ldc + row + 8] = v3;
            } else {
                *(float2*)(C + (size_t)row * ldc + col)       = make_float2(v0, v1);
                *(float2*)(C + (size_t)(row + 8) * ldc + col) = make_float2(v2, v3);
                if (SYM && xb != yb) {
                    C[(size_t)col * ldc + row]           = v0;
                    C[(size_t)(col + 1) * ldc + row]     = v1;
                    C[(size_t)col * ldc + row + 8]       = v2;
                    C[(size_t)(col + 1) * ldc + row + 8] = v3;
                }
            }
        }
    }
}

// ---------------------------------------------------------------------------
__global__ void k_transpose3(const float* __restrict__ i0, float* __restrict__ o0,
                             const float* __restrict__ i1, float* __restrict__ o1,
                             const float* __restrict__ i2, float* __restrict__ o2) {
    __shared__ float t[32][33];
    const float* in = (blockIdx.z == 0) ? i0 : (blockIdx.z == 1) ? i1 : i2;
    float* out      = (blockIdx.z == 0) ? o0 : (blockIdx.z == 1) ? o1 : o2;
    const int C = HH_ * DD_, R = DD_;
    int bx = blockIdx.x * 32, by = blockIdx.y * 32;
    #pragma unroll
    for (int i = 0; i < 32; i += 8)
        t[threadIdx.y + i][threadIdx.x] = in[(size_t)(by + threadIdx.y + i) * C + bx + threadIdx.x];
    __syncthreads();
    #pragma unroll
    for (int i = 0; i < 32; i += 8)
        out[(size_t)(bx + threadIdx.y + i) * R + by + threadIdx.x] = t[threadIdx.x][threadIdx.y + i];
}

// ---------------------------------------------------------------------------
__global__ void k_prepWg(const float* __restrict__ Wg, float* __restrict__ wgT,
                         const float* __restrict__ bo, float* __restrict__ b2) {
    if (blockIdx.x < 4) {
        __shared__ float t[32][33];
        int bx = blockIdx.x * 32, by = blockIdx.y * 32;
        #pragma unroll
        for (int i = 0; i < 32; i += 8)
            t[threadIdx.y + i][threadIdx.x] = Wg[(size_t)(by + threadIdx.y + i) * DD_ + bx + threadIdx.x];
        __syncthreads();
        #pragma unroll
        for (int i = 0; i < 32; i += 8)
            wgT[(size_t)(bx + threadIdx.y + i) * DD_ + by + threadIdx.x] = t[threadIdx.x][threadIdx.y + i];
    } else if (blockIdx.y == 0) {
        int j = threadIdx.y * 32 + threadIdx.x;
        if (j < DD_) {
            float s = 0.0f;
            for (int k = 0; k < DD_; k++) s += bo[k] * Wg[k * DD_ + j];
            b2[j] = s;
        }
    }
}

// ---------------------------------------------------------------------------
__global__ void k_embed_add(const float* __restrict__ F_c,
                            const int*   __restrict__ t,
                            float*       __restrict__ c) {
    int bn = blockIdx.x;
    int b  = bn >> 10;
    int n  = bn & 1023;
    float tv = (float)t[b];
    const float kC = logf(1000.0f) / 511.0f;
    int   i = (n < 512) ? n : (n - 512);
    float f = __expf(-(float)i * kC);
    float e = tv * f;
    float emb = (n < 512) ? sinf(e) : cosf(e);
    size_t base = (size_t)bn * DD_;
    int d = threadIdx.x;
    c[base + d] = F_c[base + d] + emb;
}

// ---------------------------------------------------------------------------
__global__ void k_rownorm(const float* __restrict__ feat,
                          float*       __restrict__ out) {
    int tid = threadIdx.x;
    size_t base = (size_t)blockIdx.x * DD_;
    float x = feat[base + tid];
    __shared__ float red[4];
    float s = x;
    #pragma unroll
    for (int o = 16; o > 0; o >>= 1) s += __shfl_xor_sync(0xffffffffu, s, o);
    if ((tid & 31) == 0) red[tid >> 5] = s;
    __syncthreads();
    float mu = (red[0] + red[1] + red[2] + red[3]) * (1.0f / 128.0f);
    float d = x - mu;
    float ss = d * d;
    #pragma unroll
    for (int o = 16; o > 0; o >>= 1) ss += __shfl_xor_sync(0xffffffffu, ss, o);
    __syncthreads();
    if ((tid & 31) == 0) red[tid >> 5] = ss;
    __syncthreads();
    float var = (red[0] + red[1] + red[2] + red[3]) * (1.0f / 127.0f);
    float inv = 1.0f / (sqrtf(var) + 1e-8f);
    out[base + tid] = d * inv;
}

// ---------------------------------------------------------------------------
extern "C" void kernel_launch(void* const* d_in, const int* in_sizes, int n_in,
                              void* d_out, int out_size) {
    const float* A_t = (const float*)d_in[0];
    const float* F_c = (const float*)d_in[1];
    const int*   t   = (const int*)  d_in[2];
    const float* Wq  = (const float*)d_in[3];
    const float* bq  = (const float*)d_in[4];
    const float* Wk  = (const float*)d_in[5];
    const float* bk  = (const float*)d_in[6];
    const float* Wv  = (const float*)d_in[7];
    const float* bv  = (const float*)d_in[8];
    const float* Wo  = (const float*)d_in[9];
    const float* bo  = (const float*)d_in[10];
    const float* Wg  = (const float*)d_in[11];
    float* out = (float*)d_out;

    float *c, *q, *k, *vt, *ctx, *hwt, *feat, *nrm;
    float *wqT, *wkT, *wvT, *w2T, *wgT, *b2;
    cudaGetSymbolAddress((void**)&c,    g_c);
    cudaGetSymbolAddress((void**)&q,    g_q);
    cudaGetSymbolAddress((void**)&k,    g_k);
    cudaGetSymbolAddress((void**)&vt,   g_vt);
    cudaGetSymbolAddress((void**)&ctx,  g_ctx);
    cudaGetSymbolAddress((void**)&hwt,  g_hwt);
    cudaGetSymbolAddress((void**)&feat, g_feat);
    cudaGetSymbolAddress((void**)&nrm,  g_norm);
    cudaGetSymbolAddress((void**)&wqT,  g_wqT);
    cudaGetSymbolAddress((void**)&wkT,  g_wkT);
    cudaGetSymbolAddress((void**)&wvT,  g_wvT);
    cudaGetSymbolAddress((void**)&w2T,  g_w2T);
    cudaGetSymbolAddress((void**)&wgT,  g_wgT);
    cudaGetSymbolAddress((void**)&b2,   g_b2);

    const size_t sBN = (size_t)NN_ * HH_ * DD_;
    const size_t sBD = (size_t)NN_ * DD_;
    const size_t sNN = (size_t)NN_ * NN_;
    const int    HD  = HH_ * DD_;
    const float  scl = 0.08838834764831845f;    // 1/sqrt(128)
    const int    FLASH_SMEM = 49664 * 4;        // ~194 KB

    cudaFuncSetAttribute(k_flash, cudaFuncAttributeMaxDynamicSharedMemorySize, FLASH_SMEM);

    // (1) QKV weight transposes
    k_transpose3<<<dim3(32, 4, 3), dim3(32, 8)>>>(Wq, wqT, Wk, wkT, Wv, wvT);

    // (2) c = F_c + t_emb
    k_embed_add<<<BSZ * NN_, DD_>>>(F_c, t, c);

    // (3-5) QKV GEMMs (tf32-rounded outputs; Q pre-scaled)
    {
        dim3 g(8, 8, BSZ);
        gemm_tb<false, true, false, true, 128, false><<<g, 256>>>(c, DD_, sBD, 0,
                                                                  wqT, DD_, 0, 0,
                                                                  q, HD, sBN, 0,
                                                                  bq, 1, scl);
        gemm_tb<false, true, false, true, 128, false><<<g, 256>>>(c, DD_, sBD, 0,
                                                                  wkT, DD_, 0, 0,
                                                                  k, HD, sBN, 0,
                                                                  bk, 1, 1.0f);
        gemm_tb<false, true, true, true, 128, false><<<g, 256>>>(c, DD_, sBD, 0,
                                                                 wvT, DD_, 0, 0,
                                                                 vt, NN_, sBN, 0,
                                                                 bv, 1, 1.0f);
    }

    // (6) fused attention: 2 q-tiles per CTA, K/V traffic halved
    k_flash<<<dim3(4, BSZ * HH_), 256, FLASH_SMEM>>>(q, k, vt, ctx);

    // (7-8) merged Wo+Wg prep
    k_prepWg<<<dim3(5, 4), dim3(32, 8)>>>(Wg, wgT, bo, b2);
    gemm_tb<false, false, false, false, 128, false><<<dim3(8, 1, 1), 256>>>(
        wgT, DD_, 0, 0, Wo, DD_, 0, 0, w2T, NN_, 0, 0,
        nullptr, 1, 1.0f);

    // (9) hwt = (ctx @ W2 + b2)^T
    {
        dim3 g(1, 8, BSZ);
        gemm_tb<false, true, true, false, 1024, false><<<g, 256>>>(ctx, HD, sBN, 0,
                                                                   w2T, NN_, 0, 0,
                                                                   hwt, NN_, sBD, 0,
                                                                   b2, 1, 1.0f);
    }
    // (10) feat = relu(A_t @ hw)
    {
        dim3 g(1, 8, BSZ);
        gemm_tb<true, false, false, false, 1024, false><<<g, 256>>>(A_t, NN_, sNN, 0,
                                                                    hwt, NN_, sBD, 0,
                                                                    feat, DD_, sBD, 0,
                                                                    nullptr, 1, 1.0f);
    }
    // (11) row normalize
    k_rownorm<<<BSZ * NN_, DD_>>>(feat, nrm);

    // (12) out = (norm @ norm^T) / 128  — symmetric blocks, mirrored
    {
        dim3 g(36, 1, BSZ);
        gemm_tb<false, false, false, false, 128, true><<<g, 256>>>(nrm, DD_, sBD, 0,
                                                                   nrm, DD_, sBD, 0,
                                                                   out, NN_, sNN, 0,
                                                                   nullptr, 1, 1.0f / 128.0f);
    }
}